// round 11
// baseline (speedup 1.0000x reference)
#include <cuda_runtime.h>
#include <cuda_fp16.h>
#include <math.h>

#define E_DIM 1024
#define H_DIM 2048
#define G3 6144            // 3*H
#define VOCAB 256
#define NBLK 148
#define NTHR 512
#define UPB 14             // hidden units per block (148*14 >= 2048)
#define NROWS_MAX (3 * UPB)   // 42

// SMEM: high-k half of weights [42][1024] fp16 | hs[2048] fp16 | flag
#define WS2_HALFS 1024
#define WS2_BYTES (NROWS_MAX * WS2_HALFS * 2)   // 86016
#define HS_OFF WS2_BYTES
#define FLG_OFF (HS_OFF + H_DIM * 2)            // 90112
#define SMEM_TOTAL (FLG_OFF + 16)

// ---------------- scratch (static device memory, no allocs) ----------------
__device__ float g_tbl[VOCAB * G3];   // W_ih@emb[v] + b_ih (+b_hh folded for r,z)
__device__ float g_h[2][H_DIM];       // hidden state fp32, double-buffered
__device__ unsigned g_cnt;            // monotonic phased barrier counter

// ---------------- sync primitives --------------------------------------------
__device__ __forceinline__ unsigned ld_acq(const unsigned* p) {
    unsigned v;
    asm volatile("ld.acquire.gpu.global.b32 %0, [%1];" : "=r"(v) : "l"(p) : "memory");
    return v;
}
__device__ __forceinline__ void red_rel_add1(unsigned* p) {
    asm volatile("red.release.gpu.global.add.u32 [%0], %1;" :: "l"(p), "r"(1u) : "memory");
}
__device__ __forceinline__ int ld_acq_cta(const int* p) {
    int v;
    asm volatile("ld.acquire.cta.u32 %0, [%1];" : "=r"(v) : "l"(p) : "memory");
    return v;
}
__device__ __forceinline__ void st_rel_cta(int* p, int v) {
    asm volatile("st.release.cta.u32 [%0], %1;" :: "l"(p), "r"(v) : "memory");
}
__device__ __forceinline__ void bar_writers(int nthreads) {
    asm volatile("bar.sync 1, %0;" :: "r"(nthreads) : "memory");
}
// 2-deep software-pipelined poll: two interleaved dependent chains halve the
// sampling period vs a single dependent load loop.
__device__ __forceinline__ void poll2(const unsigned* p, unsigned tgt) {
    unsigned a = ld_acq(p);
    if (a >= tgt) return;
    unsigned b = ld_acq(p);
    for (;;) {
        if (a >= tgt) break;
        a = ld_acq(p);
        if (b >= tgt) break;
        b = ld_acq(p);
    }
}

// ---------------- packed f32x2 helpers ---------------------------------------
__device__ __forceinline__ unsigned long long pk(float x, float y) {
    unsigned long long r;
    asm("mov.b64 %0, {%1, %2};" : "=l"(r) : "f"(x), "f"(y));
    return r;
}
__device__ __forceinline__ float2 unpk(unsigned long long v) {
    float2 r;
    asm("mov.b64 {%0, %1}, %2;" : "=f"(r.x), "=f"(r.y) : "l"(v));
    return r;
}
__device__ __forceinline__ void fma2(unsigned long long& d,
                                     unsigned long long a, unsigned long long b) {
    asm("fma.rn.f32x2 %0, %1, %2, %0;" : "+l"(d) : "l"(a), "l"(b));
}
__device__ __forceinline__ void dotq(uint4 w,
    unsigned long long hp0, unsigned long long hp1,
    unsigned long long hp2, unsigned long long hp3,
    unsigned long long& aA, unsigned long long& aB) {
    float2 f0 = __half22float2(*(__half2*)&w.x);
    float2 f1 = __half22float2(*(__half2*)&w.y);
    float2 f2 = __half22float2(*(__half2*)&w.z);
    float2 f3 = __half22float2(*(__half2*)&w.w);
    fma2(aA, pk(f0.x, f0.y), hp0);
    fma2(aB, pk(f1.x, f1.y), hp1);
    fma2(aA, pk(f2.x, f2.y), hp2);
    fma2(aB, pk(f3.x, f3.y), hp3);
}
__device__ __forceinline__ uint4 pack4(float4 a, float4 b) {
    uint4 r; __half2 h;
    h = __floats2half2_rn(a.x, a.y); r.x = *(unsigned*)&h;
    h = __floats2half2_rn(a.z, a.w); r.y = *(unsigned*)&h;
    h = __floats2half2_rn(b.x, b.y); r.z = *(unsigned*)&h;
    h = __floats2half2_rn(b.z, b.w); r.w = *(unsigned*)&h;
    return r;
}

// ---------------- kernel 1: ih table GEMM + state/counter init --------------
__global__ __launch_bounds__(256) void tbl_kernel(
    const float* __restrict__ emb,
    const float* __restrict__ w_ih,
    const float* __restrict__ b_ih,
    const float* __restrict__ b_hh)
{
    __shared__ float Es[32][33];
    __shared__ float Ws[64][33];
    const int tid = threadIdx.x;
    const int j0 = blockIdx.x * 64;
    const int v0 = blockIdx.y * 32;

    if (blockIdx.x == 0 && blockIdx.y == 0) {
        for (int i = tid; i < 2 * H_DIM; i += 256) ((float*)g_h)[i] = 0.f;
        if (tid == 0) g_cnt = 0u;
    }

    float acc[8] = {0.f, 0.f, 0.f, 0.f, 0.f, 0.f, 0.f, 0.f};
    const int jj = tid & 63;
    const int vb = (tid >> 6) * 8;

    for (int k0 = 0; k0 < E_DIM; k0 += 32) {
        __syncthreads();
        #pragma unroll
        for (int p = 0; p < 4; p++) {
            int idx = tid + p * 256;
            Es[idx >> 5][idx & 31] = emb[(size_t)(v0 + (idx >> 5)) * E_DIM + k0 + (idx & 31)];
        }
        #pragma unroll
        for (int p = 0; p < 8; p++) {
            int idx = tid + p * 256;
            Ws[idx >> 5][idx & 31] = w_ih[(size_t)(j0 + (idx >> 5)) * E_DIM + k0 + (idx & 31)];
        }
        __syncthreads();
        #pragma unroll
        for (int kk = 0; kk < 32; kk++) {
            float w = Ws[jj][kk];
            #pragma unroll
            for (int r = 0; r < 8; r++) acc[r] += w * Es[vb + r][kk];
        }
    }
    const int j = j0 + jj;
    float bias = b_ih[j] + ((j < 2 * H_DIM) ? b_hh[j] : 0.f);
    #pragma unroll
    for (int r = 0; r < 8; r++)
        g_tbl[(size_t)(v0 + vb + r) * G3 + j] = acc[r] + bias;
}

// ---------------- kernel 2: persistent GRU ----------------------------------
// Warp w (w<nu) owns unit u = b*14 + w: weights k<1024 in 48 regs, k>=1024 in
// SMEM fp16; h staged to SMEM fp16 (recurrent h stays fp32 in lane0 reg).
// Detector warp 15 polls the global counter (2-deep pipelined) and publishes
// an SMEM flag; warps spin on LDS. Arrival = writers-only named bar + one
// release-RED by warp0. One __syncthreads per step (hs handoff).
__global__ void __launch_bounds__(NTHR, 1) gru_kernel(
    const int*   __restrict__ x,
    const int*   __restrict__ lenp,
    const float* __restrict__ w_hh,    // [G3, H] fp32
    const float* __restrict__ b_hh,    // [G3]
    const float* __restrict__ dec_emb, // [128, E]
    float*       __restrict__ out,     // [E + H]
    int n_x)
{
    extern __shared__ __align__(16) unsigned char smem_raw[];
    __half* ws   = (__half*)smem_raw;              // [42][1024] high-k weights
    __half* hs   = (__half*)(smem_raw + HS_OFF);   // [2048] staged h (fp16)
    int*    flag = (int*)(smem_raw + FLG_OFF);

    const int tid  = threadIdx.x;
    const int b    = blockIdx.x;
    const int lane = tid & 31;
    const int wid  = tid >> 5;

    const int u0 = b * UPB;
    int nu = H_DIM - u0;
    if (nu > UPB) nu = UPB;
    if (nu < 0) nu = 0;
    const bool writer = (wid < nu);
    const int u = u0 + wid;

    // ---- prologue: low-k halves -> registers, high-k halves -> SMEM ----
    if (tid == 0) *flag = 0;
    uint4 wreg[12];   // [row*4 + c], c = 0..3 covers k in [0,1024)
    if (writer) {
        #pragma unroll
        for (int r = 0; r < 3; r++) {
            const float4* src = (const float4*)(w_hh + (size_t)(r * H_DIM + u) * H_DIM);
            #pragma unroll
            for (int c = 0; c < 4; c++) {
                float4 a = __ldcs(src + c * 64 + lane * 2);
                float4 q = __ldcs(src + c * 64 + lane * 2 + 1);
                wreg[r * 4 + c] = pack4(a, q);
            }
            uint4* dst = (uint4*)(ws + (size_t)(3 * wid + r) * WS2_HALFS);
            #pragma unroll
            for (int c = 0; c < 4; c++) {
                float4 a = __ldcs(src + 256 + c * 64 + lane * 2);
                float4 q = __ldcs(src + 256 + c * 64 + lane * 2 + 1);
                dst[c * 32 + lane] = pack4(a, q);
            }
        }
    }
    __syncthreads();   // flag init + nothing else pending

    float bhn = 0.f;
    if (writer && lane == 0) bhn = __ldg(&b_hh[2 * H_DIM + u]);
    float hold = 0.f;   // fp32 recurrent h for this unit (lane0)

    int steps = lenp[0] + 1;
    if (steps > n_x) steps = n_x;

    const uint4* wrow0 = (const uint4*)(ws + (size_t)(3 * wid)     * WS2_HALFS);
    const uint4* wrow1 = (const uint4*)(ws + (size_t)(3 * wid + 1) * WS2_HALFS);
    const uint4* wrow2 = (const uint4*)(ws + (size_t)(3 * wid + 2) * WS2_HALFS);
    const uint4* hs16 = (const uint4*)hs;

    unsigned target = 0;

    for (int t = 0; t < steps; ++t) {
        // hoisted step-t constants: L2 latency hides under the flag spin
        float ih_r = 0.f, ih_z = 0.f, ih_n = 0.f;
        if (writer && lane == 0) {
            const int xt = __ldg(&x[t]);
            const float* __restrict__ tbl = g_tbl + (size_t)xt * G3;
            ih_r = __ldg(&tbl[u]);
            ih_z = __ldg(&tbl[u + H_DIM]);
            ih_n = __ldg(&tbl[u + 2 * H_DIM]);
        }

        // ---- detect (warp 15 lane 0), publish via SMEM flag ----
        if (wid == 15 && lane == 0) {
            poll2(&g_cnt, target);
            st_rel_cta(flag, t + 1);
        }
        // all threads spin on the flag (LDS broadcast, ~30cyc release)
        while (ld_acq_cta(flag) < t + 1) { }

        const int prev = t & 1;

        // ---- stage h(t-1) into SMEM as fp16 (512 threads x 4 floats) ----
        {
            float4 v = __ldcg(((const float4*)g_h[prev]) + tid);
            uint2 o; __half2 h;
            h = __floats2half2_rn(v.x, v.y); o.x = *(unsigned*)&h;
            h = __floats2half2_rn(v.z, v.w); o.y = *(unsigned*)&h;
            ((uint2*)hs)[tid] = o;
        }
        __syncthreads();   // hs complete before compute reads

        if (writer) {
            unsigned long long a00 = 0ull, a01 = 0ull;
            unsigned long long a10 = 0ull, a11 = 0ull;
            unsigned long long a20 = 0ull, a21 = 0ull;
            #pragma unroll
            for (int c = 0; c < 8; c++) {
                uint4 hw = hs16[c * 32 + lane];   // 8 fp16 h values
                float2 g0 = __half22float2(*(__half2*)&hw.x);
                float2 g1 = __half22float2(*(__half2*)&hw.y);
                float2 g2 = __half22float2(*(__half2*)&hw.z);
                float2 g3 = __half22float2(*(__half2*)&hw.w);
                unsigned long long hp0 = pk(g0.x, g0.y);
                unsigned long long hp1 = pk(g1.x, g1.y);
                unsigned long long hp2 = pk(g2.x, g2.y);
                unsigned long long hp3 = pk(g3.x, g3.y);
                uint4 w0 = (c < 4) ? wreg[0 * 4 + c] : wrow0[(c - 4) * 32 + lane];
                uint4 w1 = (c < 4) ? wreg[1 * 4 + c] : wrow1[(c - 4) * 32 + lane];
                uint4 w2 = (c < 4) ? wreg[2 * 4 + c] : wrow2[(c - 4) * 32 + lane];
                dotq(w0, hp0, hp1, hp2, hp3, a00, a01);
                dotq(w1, hp0, hp1, hp2, hp3, a10, a11);
                dotq(w2, hp0, hp1, hp2, hp3, a20, a21);
            }
            float2 s;
            float a0, a1, a2;
            s = unpk(a00); a0 = s.x + s.y;  s = unpk(a01); a0 += s.x + s.y;
            s = unpk(a10); a1 = s.x + s.y;  s = unpk(a11); a1 += s.x + s.y;
            s = unpk(a20); a2 = s.x + s.y;  s = unpk(a21); a2 += s.x + s.y;
            #pragma unroll
            for (int o = 16; o; o >>= 1) {
                a0 += __shfl_xor_sync(0xffffffffu, a0, o);
                a1 += __shfl_xor_sync(0xffffffffu, a1, o);
                a2 += __shfl_xor_sync(0xffffffffu, a2, o);
            }
            if (lane == 0) {
                float r = 1.f / (1.f + __expf(-(a0 + ih_r)));  // biases folded in tbl
                float z = 1.f / (1.f + __expf(-(a1 + ih_z)));
                float v = ih_n + r * (a2 + bhn);
                float e = __expf(2.f * v);
                float n = 1.f - __fdividef(2.f, e + 1.f);       // tanh(v)
                float hnew = (1.f - z) * n + z * hold;
                hold = hnew;
                __stcg(&g_h[prev ^ 1][u], hnew);
            }
            // writers-only arrival, then one release-RED by warp 0
            bar_writers(nu * 32);
            if (wid == 0 && lane == 0) red_rel_add1(&g_cnt);
        } else if (nu == 0 && wid == 0 && lane == 0) {
            red_rel_add1(&g_cnt);   // block with no units still arrives
        }

        target += NBLK;
    }

    if (b == 0) {
        if (tid == 0) poll2(&g_cnt, target);
        __syncthreads();
        const int last = steps & 1;
        for (int i = tid; i < E_DIM; i += NTHR) out[i] = dec_emb[2 * E_DIM + i];
        for (int i = tid; i < H_DIM; i += NTHR) out[E_DIM + i] = __ldcg(&g_h[last][i]);
    }
}

// ---------------- launch ----------------------------------------------------
extern "C" void kernel_launch(void* const* d_in, const int* in_sizes, int n_in,
                              void* d_out, int out_size) {
    const int*   x       = (const int*)d_in[0];
    const int*   lenp    = (const int*)d_in[1];
    const float* enc_emb = (const float*)d_in[2];
    const float* w_ih    = (const float*)d_in[3];
    const float* w_hh    = (const float*)d_in[4];
    const float* b_ih    = (const float*)d_in[5];
    const float* b_hh    = (const float*)d_in[6];
    const float* dec_emb = (const float*)d_in[7];
    float* out = (float*)d_out;
    const int n_x = in_sizes[0];

    static int attr_set = 0;
    if (!attr_set) {
        cudaFuncSetAttribute(gru_kernel, cudaFuncAttributeMaxDynamicSharedMemorySize,
                             SMEM_TOTAL);
        attr_set = 1;
    }

    dim3 tgrid(G3 / 64, VOCAB / 32);   // 96 x 8
    tbl_kernel<<<tgrid, 256>>>(enc_emb, w_ih, b_ih, b_hh);
    gru_kernel<<<NBLK, NTHR, SMEM_TOTAL>>>(x, lenp, w_hh, b_hh, dec_emb, out, n_x);
}

// round 14
// speedup vs baseline: 1.2090x; 1.2090x over previous
#include <cuda_runtime.h>
#include <cuda_fp16.h>
#include <math.h>

#define E_DIM 1024
#define H_DIM 2048
#define G3 6144            // 3*H
#define VOCAB 256
#define NBLK 128
#define NTHR 512
#define UPB 16             // hidden units per block: 128*16 = 2048 exactly
#define NROWS (3 * UPB)    // 48 rows per block

// SMEM: high-k half of weights [48][1024] fp16 | hs[2048] fp16
#define WS2_HALFS 1024
#define WS2_BYTES (NROWS * WS2_HALFS * 2)   // 98304
#define HS_OFF WS2_BYTES
#define SMEM_TOTAL (HS_OFF + H_DIM * 2)     // 102400

// ---------------- scratch (static device memory, no allocs) ----------------
__device__ float g_tbl[VOCAB * G3];   // W_ih@emb[v] + b_ih (+b_hh folded for r,z)
__device__ float g_h[2][H_DIM];       // hidden state fp32, double-buffered
__device__ unsigned g_cnt;            // monotonic phased barrier counter

// ---------------- sync primitives --------------------------------------------
__device__ __forceinline__ unsigned ld_acq(const unsigned* p) {
    unsigned v;
    asm volatile("ld.acquire.gpu.global.b32 %0, [%1];" : "=r"(v) : "l"(p) : "memory");
    return v;
}
__device__ __forceinline__ void red_rel_add1(unsigned* p) {
    asm volatile("red.release.gpu.global.add.u32 [%0], %1;" :: "l"(p), "r"(1u) : "memory");
}
// 2-deep software-pipelined poll: two interleaved dependent chains halve the
// sampling period vs a single dependent-load loop.
__device__ __forceinline__ void poll2(const unsigned* p, unsigned tgt) {
    unsigned a = ld_acq(p);
    if (a >= tgt) return;
    unsigned b = ld_acq(p);
    for (;;) {
        if (a >= tgt) break;
        a = ld_acq(p);
        if (b >= tgt) break;
        b = ld_acq(p);
    }
}

// ---------------- packed f32x2 helpers ---------------------------------------
__device__ __forceinline__ unsigned long long pk(float x, float y) {
    unsigned long long r;
    asm("mov.b64 %0, {%1, %2};" : "=l"(r) : "f"(x), "f"(y));
    return r;
}
__device__ __forceinline__ float2 unpk(unsigned long long v) {
    float2 r;
    asm("mov.b64 {%0, %1}, %2;" : "=f"(r.x), "=f"(r.y) : "l"(v));
    return r;
}
__device__ __forceinline__ void fma2(unsigned long long& d,
                                     unsigned long long a, unsigned long long b) {
    asm("fma.rn.f32x2 %0, %1, %2, %0;" : "+l"(d) : "l"(a), "l"(b));
}
__device__ __forceinline__ void dotq(uint4 w,
    unsigned long long hp0, unsigned long long hp1,
    unsigned long long hp2, unsigned long long hp3,
    unsigned long long& aA, unsigned long long& aB) {
    float2 f0 = __half22float2(*(__half2*)&w.x);
    float2 f1 = __half22float2(*(__half2*)&w.y);
    float2 f2 = __half22float2(*(__half2*)&w.z);
    float2 f3 = __half22float2(*(__half2*)&w.w);
    fma2(aA, pk(f0.x, f0.y), hp0);
    fma2(aB, pk(f1.x, f1.y), hp1);
    fma2(aA, pk(f2.x, f2.y), hp2);
    fma2(aB, pk(f3.x, f3.y), hp3);
}
__device__ __forceinline__ uint4 pack4(float4 a, float4 b) {
    uint4 r; __half2 h;
    h = __floats2half2_rn(a.x, a.y); r.x = *(unsigned*)&h;
    h = __floats2half2_rn(a.z, a.w); r.y = *(unsigned*)&h;
    h = __floats2half2_rn(b.x, b.y); r.z = *(unsigned*)&h;
    h = __floats2half2_rn(b.z, b.w); r.w = *(unsigned*)&h;
    return r;
}

// ---------------- kernel 1: ih table GEMM + state/counter init --------------
__global__ __launch_bounds__(256) void tbl_kernel(
    const float* __restrict__ emb,
    const float* __restrict__ w_ih,
    const float* __restrict__ b_ih,
    const float* __restrict__ b_hh)
{
    __shared__ float Es[32][33];
    __shared__ float Ws[64][33];
    const int tid = threadIdx.x;
    const int j0 = blockIdx.x * 64;
    const int v0 = blockIdx.y * 32;

    if (blockIdx.x == 0 && blockIdx.y == 0) {
        for (int i = tid; i < 2 * H_DIM; i += 256) ((float*)g_h)[i] = 0.f;
        if (tid == 0) g_cnt = 0u;
    }

    float acc[8] = {0.f, 0.f, 0.f, 0.f, 0.f, 0.f, 0.f, 0.f};
    const int jj = tid & 63;
    const int vb = (tid >> 6) * 8;

    for (int k0 = 0; k0 < E_DIM; k0 += 32) {
        __syncthreads();
        #pragma unroll
        for (int p = 0; p < 4; p++) {
            int idx = tid + p * 256;
            Es[idx >> 5][idx & 31] = emb[(size_t)(v0 + (idx >> 5)) * E_DIM + k0 + (idx & 31)];
        }
        #pragma unroll
        for (int p = 0; p < 8; p++) {
            int idx = tid + p * 256;
            Ws[idx >> 5][idx & 31] = w_ih[(size_t)(j0 + (idx >> 5)) * E_DIM + k0 + (idx & 31)];
        }
        __syncthreads();
        #pragma unroll
        for (int kk = 0; kk < 32; kk++) {
            float w = Ws[jj][kk];
            #pragma unroll
            for (int r = 0; r < 8; r++) acc[r] += w * Es[vb + r][kk];
        }
    }
    const int j = j0 + jj;
    float bias = b_ih[j] + ((j < 2 * H_DIM) ? b_hh[j] : 0.f);
    #pragma unroll
    for (int r = 0; r < 8; r++)
        g_tbl[(size_t)(v0 + vb + r) * G3 + j] = acc[r] + bias;
}

// ---------------- kernel 2: persistent GRU (proven counter skeleton) --------
// 128 blocks x 16 warps; warp w of block b owns unit u = b*16 + w (every warp
// is a writer). Weights k<1024 in 48 regs (packed half2), k>=1024 in SMEM
// fp16. h staged into SMEM as fp16; recurrent h stays fp32 in lane0's
// register. Grid sync = monotonic counter (tid0 poll2 + one RED per block).
__global__ void __launch_bounds__(NTHR, 1) gru_kernel(
    const int*   __restrict__ x,
    const int*   __restrict__ lenp,
    const float* __restrict__ w_hh,    // [G3, H] fp32
    const float* __restrict__ b_hh,    // [G3]
    const float* __restrict__ dec_emb, // [128, E]
    float*       __restrict__ out,     // [E + H]
    int n_x)
{
    extern __shared__ __align__(16) unsigned char smem_raw[];
    __half* ws = (__half*)smem_raw;              // [48][1024] high-k weights
    __half* hs = (__half*)(smem_raw + HS_OFF);   // [2048] staged h (fp16)

    const int tid  = threadIdx.x;
    const int b    = blockIdx.x;
    const int lane = tid & 31;
    const int wid  = tid >> 5;

    const int u = b * UPB + wid;       // this warp's hidden unit (always valid)

    // ---- prologue: low-k halves -> registers, high-k halves -> SMEM ----
    uint4 wreg[12];   // [row*4 + c], c = 0..3 covers k in [0,1024)
    #pragma unroll
    for (int r = 0; r < 3; r++) {
        const float4* src = (const float4*)(w_hh + (size_t)(r * H_DIM + u) * H_DIM);
        #pragma unroll
        for (int c = 0; c < 4; c++) {
            float4 a = __ldcs(src + c * 64 + lane * 2);
            float4 q = __ldcs(src + c * 64 + lane * 2 + 1);
            wreg[r * 4 + c] = pack4(a, q);
        }
        uint4* dst = (uint4*)(ws + (size_t)(3 * wid + r) * WS2_HALFS);
        #pragma unroll
        for (int c = 0; c < 4; c++) {
            float4 a = __ldcs(src + 256 + c * 64 + lane * 2);
            float4 q = __ldcs(src + 256 + c * 64 + lane * 2 + 1);
            dst[c * 32 + lane] = pack4(a, q);
        }
    }

    float bhn = (lane == 0) ? __ldg(&b_hh[2 * H_DIM + u]) : 0.f;
    float hold = 0.f;   // fp32 recurrent h for this unit (lane0)

    int steps = lenp[0] + 1;
    if (steps > n_x) steps = n_x;

    const uint4* wrow0 = (const uint4*)(ws + (size_t)(3 * wid)     * WS2_HALFS);
    const uint4* wrow1 = (const uint4*)(ws + (size_t)(3 * wid + 1) * WS2_HALFS);
    const uint4* wrow2 = (const uint4*)(ws + (size_t)(3 * wid + 2) * WS2_HALFS);
    const uint4* hs16 = (const uint4*)hs;

    unsigned target = 0;

    for (int t = 0; t < steps; ++t) {
        // hoisted step-t constants: L2 latency hides under the counter poll
        float ih_r = 0.f, ih_z = 0.f, ih_n = 0.f;
        if (lane == 0) {
            const int xt = __ldg(&x[t]);
            const float* __restrict__ tbl = g_tbl + (size_t)xt * G3;
            ih_r = __ldg(&tbl[u]);
            ih_z = __ldg(&tbl[u + H_DIM]);
            ih_n = __ldg(&tbl[u + 2 * H_DIM]);
        }

        // ---- wait: all blocks finished step t-1 ----
        if (tid == 0) poll2(&g_cnt, target);
        __syncthreads();

        const int prev = t & 1;

        // ---- stage h(t-1) into SMEM as fp16 (512 threads x 4 floats) ----
        {
            float4 v = __ldcg(((const float4*)g_h[prev]) + tid);
            uint2 o; __half2 h;
            h = __floats2half2_rn(v.x, v.y); o.x = *(unsigned*)&h;
            h = __floats2half2_rn(v.z, v.w); o.y = *(unsigned*)&h;
            ((uint2*)hs)[tid] = o;
        }
        __syncthreads();   // hs complete before compute reads

        {
            unsigned long long a00 = 0ull, a01 = 0ull;
            unsigned long long a10 = 0ull, a11 = 0ull;
            unsigned long long a20 = 0ull, a21 = 0ull;
            #pragma unroll
            for (int c = 0; c < 8; c++) {
                uint4 hw = hs16[c * 32 + lane];   // 8 fp16 h values
                float2 g0 = __half22float2(*(__half2*)&hw.x);
                float2 g1 = __half22float2(*(__half2*)&hw.y);
                float2 g2 = __half22float2(*(__half2*)&hw.z);
                float2 g3 = __half22float2(*(__half2*)&hw.w);
                unsigned long long hp0 = pk(g0.x, g0.y);
                unsigned long long hp1 = pk(g1.x, g1.y);
                unsigned long long hp2 = pk(g2.x, g2.y);
                unsigned long long hp3 = pk(g3.x, g3.y);
                uint4 w0 = (c < 4) ? wreg[0 * 4 + c] : wrow0[(c - 4) * 32 + lane];
                uint4 w1 = (c < 4) ? wreg[1 * 4 + c] : wrow1[(c - 4) * 32 + lane];
                uint4 w2 = (c < 4) ? wreg[2 * 4 + c] : wrow2[(c - 4) * 32 + lane];
                dotq(w0, hp0, hp1, hp2, hp3, a00, a01);
                dotq(w1, hp0, hp1, hp2, hp3, a10, a11);
                dotq(w2, hp0, hp1, hp2, hp3, a20, a21);
            }
            float2 s;
            float a0, a1, a2;
            s = unpk(a00); a0 = s.x + s.y;  s = unpk(a01); a0 += s.x + s.y;
            s = unpk(a10); a1 = s.x + s.y;  s = unpk(a11); a1 += s.x + s.y;
            s = unpk(a20); a2 = s.x + s.y;  s = unpk(a21); a2 += s.x + s.y;
            #pragma unroll
            for (int o = 16; o; o >>= 1) {
                a0 += __shfl_xor_sync(0xffffffffu, a0, o);
                a1 += __shfl_xor_sync(0xffffffffu, a1, o);
                a2 += __shfl_xor_sync(0xffffffffu, a2, o);
            }
            if (lane == 0) {
                float r = 1.f / (1.f + __expf(-(a0 + ih_r)));  // biases folded in tbl
                float z = 1.f / (1.f + __expf(-(a1 + ih_z)));
                float v = ih_n + r * (a2 + bhn);
                float e = __expf(2.f * v);
                float n = 1.f - __fdividef(2.f, e + 1.f);       // tanh(v)
                float hnew = (1.f - z) * n + z * hold;
                hold = hnew;
                __stcg(&g_h[prev ^ 1][u], hnew);
            }
        }
        __syncthreads();   // all writers' stores done before arrival

        // ---- arrive: one release-RED per block ----
        if (tid == 0) red_rel_add1(&g_cnt);
        target += NBLK;
    }

    if (b == 0) {
        if (tid == 0) poll2(&g_cnt, target);
        __syncthreads();
        const int last = steps & 1;
        for (int i = tid; i < E_DIM; i += NTHR) out[i] = dec_emb[2 * E_DIM + i];
        for (int i = tid; i < H_DIM; i += NTHR) out[E_DIM + i] = __ldcg(&g_h[last][i]);
    }
}

// ---------------- launch ----------------------------------------------------
extern "C" void kernel_launch(void* const* d_in, const int* in_sizes, int n_in,
                              void* d_out, int out_size) {
    const int*   x       = (const int*)d_in[0];
    const int*   lenp    = (const int*)d_in[1];
    const float* enc_emb = (const float*)d_in[2];
    const float* w_ih    = (const float*)d_in[3];
    const float* w_hh    = (const float*)d_in[4];
    const float* b_ih    = (const float*)d_in[5];
    const float* b_hh    = (const float*)d_in[6];
    const float* dec_emb = (const float*)d_in[7];
    float* out = (float*)d_out;
    const int n_x = in_sizes[0];

    static int attr_set = 0;
    if (!attr_set) {
        cudaFuncSetAttribute(gru_kernel, cudaFuncAttributeMaxDynamicSharedMemorySize,
                             SMEM_TOTAL);
        attr_set = 1;
    }

    dim3 tgrid(G3 / 64, VOCAB / 32);   // 96 x 8
    tbl_kernel<<<tgrid, 256>>>(enc_emb, w_ih, b_ih, b_hh);
    gru_kernel<<<NBLK, NTHR, SMEM_TOTAL>>>(x, lenp, w_hh, b_hh, dec_emb, out, n_x);
}

// round 15
// speedup vs baseline: 1.2100x; 1.0008x over previous
#include <cuda_runtime.h>
#include <cuda_fp16.h>
#include <math.h>

#define E_DIM 1024
#define H_DIM 2048
#define G3 6144            // 3*H
#define VOCAB 256
#define NBLK 128
#define NTHR 512
#define UPB 16             // hidden units per block: 128*16 = 2048 exactly
#define NROWS (3 * UPB)    // 48 rows per block

// SMEM: high-k half of weights [48][1024] fp16 | hs[2048] fp16
#define WS2_HALFS 1024
#define WS2_BYTES (NROWS * WS2_HALFS * 2)   // 98304
#define HS_OFF WS2_BYTES
#define SMEM_TOTAL (HS_OFF + H_DIM * 2)     // 102400

// ---------------- scratch (static device memory, no allocs) ----------------
__device__ float g_tbl[VOCAB * G3];   // W_ih@emb[v] + b_ih (+b_hh folded for r,z)
__device__ float g_h[2][H_DIM];       // hidden state fp32, double-buffered
__device__ unsigned g_cnt;            // monotonic phased barrier counter

// ---------------- sync primitives --------------------------------------------
__device__ __forceinline__ unsigned ld_acq(const unsigned* p) {
    unsigned v;
    asm volatile("ld.acquire.gpu.global.b32 %0, [%1];" : "=r"(v) : "l"(p) : "memory");
    return v;
}
__device__ __forceinline__ void red_rel_add1(unsigned* p) {
    asm volatile("red.release.gpu.global.add.u32 [%0], %1;" :: "l"(p), "r"(1u) : "memory");
}
// 2-deep software-pipelined poll: two interleaved dependent chains halve the
// sampling period vs a single dependent-load loop.
__device__ __forceinline__ void poll2(const unsigned* p, unsigned tgt) {
    unsigned a = ld_acq(p);
    if (a >= tgt) return;
    unsigned b = ld_acq(p);
    for (;;) {
        if (a >= tgt) break;
        a = ld_acq(p);
        if (b >= tgt) break;
        b = ld_acq(p);
    }
}

// ---------------- packed f32x2 helpers ---------------------------------------
__device__ __forceinline__ unsigned long long pk(float x, float y) {
    unsigned long long r;
    asm("mov.b64 %0, {%1, %2};" : "=l"(r) : "f"(x), "f"(y));
    return r;
}
__device__ __forceinline__ float2 unpk(unsigned long long v) {
    float2 r;
    asm("mov.b64 {%0, %1}, %2;" : "=f"(r.x), "=f"(r.y) : "l"(v));
    return r;
}
__device__ __forceinline__ void fma2(unsigned long long& d,
                                     unsigned long long a, unsigned long long b) {
    asm("fma.rn.f32x2 %0, %1, %2, %0;" : "+l"(d) : "l"(a), "l"(b));
}
__device__ __forceinline__ void dotq(uint4 w,
    unsigned long long hp0, unsigned long long hp1,
    unsigned long long hp2, unsigned long long hp3,
    unsigned long long& aA, unsigned long long& aB) {
    float2 f0 = __half22float2(*(__half2*)&w.x);
    float2 f1 = __half22float2(*(__half2*)&w.y);
    float2 f2 = __half22float2(*(__half2*)&w.z);
    float2 f3 = __half22float2(*(__half2*)&w.w);
    fma2(aA, pk(f0.x, f0.y), hp0);
    fma2(aB, pk(f1.x, f1.y), hp1);
    fma2(aA, pk(f2.x, f2.y), hp2);
    fma2(aB, pk(f3.x, f3.y), hp3);
}
__device__ __forceinline__ uint4 pack4(float4 a, float4 b) {
    uint4 r; __half2 h;
    h = __floats2half2_rn(a.x, a.y); r.x = *(unsigned*)&h;
    h = __floats2half2_rn(a.z, a.w); r.y = *(unsigned*)&h;
    h = __floats2half2_rn(b.x, b.y); r.z = *(unsigned*)&h;
    h = __floats2half2_rn(b.z, b.w); r.w = *(unsigned*)&h;
    return r;
}

// ---------------- kernel 1: ih table GEMM + state/counter init --------------
__global__ __launch_bounds__(256) void tbl_kernel(
    const float* __restrict__ emb,
    const float* __restrict__ w_ih,
    const float* __restrict__ b_ih,
    const float* __restrict__ b_hh)
{
    __shared__ float Es[32][33];
    __shared__ float Ws[64][33];
    const int tid = threadIdx.x;
    const int j0 = blockIdx.x * 64;
    const int v0 = blockIdx.y * 32;

    if (blockIdx.x == 0 && blockIdx.y == 0) {
        for (int i = tid; i < 2 * H_DIM; i += 256) ((float*)g_h)[i] = 0.f;
        if (tid == 0) g_cnt = 0u;
    }

    float acc[8] = {0.f, 0.f, 0.f, 0.f, 0.f, 0.f, 0.f, 0.f};
    const int jj = tid & 63;
    const int vb = (tid >> 6) * 8;

    for (int k0 = 0; k0 < E_DIM; k0 += 32) {
        __syncthreads();
        #pragma unroll
        for (int p = 0; p < 4; p++) {
            int idx = tid + p * 256;
            Es[idx >> 5][idx & 31] = emb[(size_t)(v0 + (idx >> 5)) * E_DIM + k0 + (idx & 31)];
        }
        #pragma unroll
        for (int p = 0; p < 8; p++) {
            int idx = tid + p * 256;
            Ws[idx >> 5][idx & 31] = w_ih[(size_t)(j0 + (idx >> 5)) * E_DIM + k0 + (idx & 31)];
        }
        __syncthreads();
        #pragma unroll
        for (int kk = 0; kk < 32; kk++) {
            float w = Ws[jj][kk];
            #pragma unroll
            for (int r = 0; r < 8; r++) acc[r] += w * Es[vb + r][kk];
        }
    }
    const int j = j0 + jj;
    float bias = b_ih[j] + ((j < 2 * H_DIM) ? b_hh[j] : 0.f);
    #pragma unroll
    for (int r = 0; r < 8; r++)
        g_tbl[(size_t)(v0 + vb + r) * G3 + j] = acc[r] + bias;
}

// ---------------- kernel 2: persistent GRU (proven counter skeleton) --------
// 128 blocks x 16 warps; warp w of block b owns unit u = b*16 + w (every warp
// is a writer). Weights k<1024 in 48 regs (packed half2), k>=1024 in SMEM
// fp16. h staged into SMEM as fp16; recurrent h stays fp32 in lane0's
// register. Grid sync = monotonic counter (tid0 poll2 + one RED per block).
__global__ void __launch_bounds__(NTHR, 1) gru_kernel(
    const int*   __restrict__ x,
    const int*   __restrict__ lenp,
    const float* __restrict__ w_hh,    // [G3, H] fp32
    const float* __restrict__ b_hh,    // [G3]
    const float* __restrict__ dec_emb, // [128, E]
    float*       __restrict__ out,     // [E + H]
    int n_x)
{
    extern __shared__ __align__(16) unsigned char smem_raw[];
    __half* ws = (__half*)smem_raw;              // [48][1024] high-k weights
    __half* hs = (__half*)(smem_raw + HS_OFF);   // [2048] staged h (fp16)

    const int tid  = threadIdx.x;
    const int b    = blockIdx.x;
    const int lane = tid & 31;
    const int wid  = tid >> 5;

    const int u = b * UPB + wid;       // this warp's hidden unit (always valid)

    // ---- prologue: low-k halves -> registers, high-k halves -> SMEM ----
    uint4 wreg[12];   // [row*4 + c], c = 0..3 covers k in [0,1024)
    #pragma unroll
    for (int r = 0; r < 3; r++) {
        const float4* src = (const float4*)(w_hh + (size_t)(r * H_DIM + u) * H_DIM);
        #pragma unroll
        for (int c = 0; c < 4; c++) {
            float4 a = __ldcs(src + c * 64 + lane * 2);
            float4 q = __ldcs(src + c * 64 + lane * 2 + 1);
            wreg[r * 4 + c] = pack4(a, q);
        }
        uint4* dst = (uint4*)(ws + (size_t)(3 * wid + r) * WS2_HALFS);
        #pragma unroll
        for (int c = 0; c < 4; c++) {
            float4 a = __ldcs(src + 256 + c * 64 + lane * 2);
            float4 q = __ldcs(src + 256 + c * 64 + lane * 2 + 1);
            dst[c * 32 + lane] = pack4(a, q);
        }
    }

    float bhn = (lane == 0) ? __ldg(&b_hh[2 * H_DIM + u]) : 0.f;
    float hold = 0.f;   // fp32 recurrent h for this unit (lane0)

    int steps = lenp[0] + 1;
    if (steps > n_x) steps = n_x;

    const uint4* wrow0 = (const uint4*)(ws + (size_t)(3 * wid)     * WS2_HALFS);
    const uint4* wrow1 = (const uint4*)(ws + (size_t)(3 * wid + 1) * WS2_HALFS);
    const uint4* wrow2 = (const uint4*)(ws + (size_t)(3 * wid + 2) * WS2_HALFS);
    const uint4* hs16 = (const uint4*)hs;

    unsigned target = 0;

    for (int t = 0; t < steps; ++t) {
        // hoisted step-t constants: L2 latency hides under the counter poll
        float ih_r = 0.f, ih_z = 0.f, ih_n = 0.f;
        if (lane == 0) {
            const int xt = __ldg(&x[t]);
            const float* __restrict__ tbl = g_tbl + (size_t)xt * G3;
            ih_r = __ldg(&tbl[u]);
            ih_z = __ldg(&tbl[u + H_DIM]);
            ih_n = __ldg(&tbl[u + 2 * H_DIM]);
        }

        // ---- wait: all blocks finished step t-1 ----
        if (tid == 0) poll2(&g_cnt, target);
        __syncthreads();

        const int prev = t & 1;

        // ---- stage h(t-1) into SMEM as fp16 (512 threads x 4 floats) ----
        {
            float4 v = __ldcg(((const float4*)g_h[prev]) + tid);
            uint2 o; __half2 h;
            h = __floats2half2_rn(v.x, v.y); o.x = *(unsigned*)&h;
            h = __floats2half2_rn(v.z, v.w); o.y = *(unsigned*)&h;
            ((uint2*)hs)[tid] = o;
        }
        __syncthreads();   // hs complete before compute reads

        {
            unsigned long long a00 = 0ull, a01 = 0ull;
            unsigned long long a10 = 0ull, a11 = 0ull;
            unsigned long long a20 = 0ull, a21 = 0ull;
            #pragma unroll
            for (int c = 0; c < 8; c++) {
                uint4 hw = hs16[c * 32 + lane];   // 8 fp16 h values
                float2 g0 = __half22float2(*(__half2*)&hw.x);
                float2 g1 = __half22float2(*(__half2*)&hw.y);
                float2 g2 = __half22float2(*(__half2*)&hw.z);
                float2 g3 = __half22float2(*(__half2*)&hw.w);
                unsigned long long hp0 = pk(g0.x, g0.y);
                unsigned long long hp1 = pk(g1.x, g1.y);
                unsigned long long hp2 = pk(g2.x, g2.y);
                unsigned long long hp3 = pk(g3.x, g3.y);
                uint4 w0 = (c < 4) ? wreg[0 * 4 + c] : wrow0[(c - 4) * 32 + lane];
                uint4 w1 = (c < 4) ? wreg[1 * 4 + c] : wrow1[(c - 4) * 32 + lane];
                uint4 w2 = (c < 4) ? wreg[2 * 4 + c] : wrow2[(c - 4) * 32 + lane];
                dotq(w0, hp0, hp1, hp2, hp3, a00, a01);
                dotq(w1, hp0, hp1, hp2, hp3, a10, a11);
                dotq(w2, hp0, hp1, hp2, hp3, a20, a21);
            }
            float2 s;
            float a0, a1, a2;
            s = unpk(a00); a0 = s.x + s.y;  s = unpk(a01); a0 += s.x + s.y;
            s = unpk(a10); a1 = s.x + s.y;  s = unpk(a11); a1 += s.x + s.y;
            s = unpk(a20); a2 = s.x + s.y;  s = unpk(a21); a2 += s.x + s.y;
            #pragma unroll
            for (int o = 16; o; o >>= 1) {
                a0 += __shfl_xor_sync(0xffffffffu, a0, o);
                a1 += __shfl_xor_sync(0xffffffffu, a1, o);
                a2 += __shfl_xor_sync(0xffffffffu, a2, o);
            }
            if (lane == 0) {
                float r = 1.f / (1.f + __expf(-(a0 + ih_r)));  // biases folded in tbl
                float z = 1.f / (1.f + __expf(-(a1 + ih_z)));
                float v = ih_n + r * (a2 + bhn);
                float e = __expf(2.f * v);
                float n = 1.f - __fdividef(2.f, e + 1.f);       // tanh(v)
                float hnew = (1.f - z) * n + z * hold;
                hold = hnew;
                __stcg(&g_h[prev ^ 1][u], hnew);
            }
        }
        __syncthreads();   // all writers' stores done before arrival

        // ---- arrive: one release-RED per block ----
        if (tid == 0) red_rel_add1(&g_cnt);
        target += NBLK;
    }

    if (b == 0) {
        if (tid == 0) poll2(&g_cnt, target);
        __syncthreads();
        const int last = steps & 1;
        for (int i = tid; i < E_DIM; i += NTHR) out[i] = dec_emb[2 * E_DIM + i];
        for (int i = tid; i < H_DIM; i += NTHR) out[E_DIM + i] = __ldcg(&g_h[last][i]);
    }
}

// ---------------- launch ----------------------------------------------------
extern "C" void kernel_launch(void* const* d_in, const int* in_sizes, int n_in,
                              void* d_out, int out_size) {
    const int*   x       = (const int*)d_in[0];
    const int*   lenp    = (const int*)d_in[1];
    const float* enc_emb = (const float*)d_in[2];
    const float* w_ih    = (const float*)d_in[3];
    const float* w_hh    = (const float*)d_in[4];
    const float* b_ih    = (const float*)d_in[5];
    const float* b_hh    = (const float*)d_in[6];
    const float* dec_emb = (const float*)d_in[7];
    float* out = (float*)d_out;
    const int n_x = in_sizes[0];

    static int attr_set = 0;
    if (!attr_set) {
        cudaFuncSetAttribute(gru_kernel, cudaFuncAttributeMaxDynamicSharedMemorySize,
                             SMEM_TOTAL);
        attr_set = 1;
    }

    dim3 tgrid(G3 / 64, VOCAB / 32);   // 96 x 8
    tbl_kernel<<<tgrid, 256>>>(enc_emb, w_ih, b_ih, b_hh);
    gru_kernel<<<NBLK, NTHR, SMEM_TOTAL>>>(x, lenp, w_hh, b_hh, dec_emb, out, n_x);
}